// round 1
// baseline (speedup 1.0000x reference)
#include <cuda_runtime.h>
#include <cuda_bf16.h>
#include <math.h>

// ---------------- problem constants ----------------
#define B_SZ 4
#define L_SEQ 2048
#define D_MODEL 258
#define N_LAYERS 4
#define D_STATE 16
#define D_CONV 4
#define D_INNER 516            // 2 * 258
#define DT_RANK 17
#define TWO_D_INNER 1032
#define XDBL_W 49              // DT_RANK + 2*D_STATE
#define NTOK (B_SZ * L_SEQ)    // 8192
#define EPS 1e-5f

// ---------------- scratch (device globals; no allocation allowed) ----------------
__device__ float g_x[NTOK * D_MODEL];       // running residual
__device__ float g_xn[NTOK * D_MODEL];      // rmsnormed x
__device__ float g_xz[NTOK * TWO_D_INNER];  // in_proj output (xi | z)
__device__ float g_xc[NTOK * D_INNER];      // conv+silu output (u)
__device__ float g_xdbl[NTOK * XDBL_W];     // x_proj output (dt_lo | B | C)
__device__ float g_dt[NTOK * D_INNER];      // softplus(dt)
__device__ float g_y[NTOK * D_INNER];       // scan output
__device__ float g_y2[NTOK * D_INNER];      // gated output

// ---------------- block reduce helper ----------------
__device__ __forceinline__ float block_reduce_sum(float v) {
    __shared__ float sh[9];
    int lane = threadIdx.x & 31, w = threadIdx.x >> 5;
    #pragma unroll
    for (int o = 16; o; o >>= 1) v += __shfl_xor_sync(0xffffffffu, v, o);
    if (lane == 0) sh[w] = v;
    __syncthreads();
    if (w == 0) {
        int nw = (blockDim.x + 31) >> 5;
        v = (lane < nw) ? sh[lane] : 0.f;
        #pragma unroll
        for (int o = 4; o; o >>= 1) v += __shfl_xor_sync(0xffffffffu, v, o);
        if (lane == 0) sh[8] = v;
    }
    __syncthreads();
    return sh[8];
}

// ---------------- rmsnorm: one block per token ----------------
__global__ void rmsnorm_kernel(const float* __restrict__ x, const float* __restrict__ w,
                               float* __restrict__ out) {
    int row = blockIdx.x;
    const float* xr = x + (size_t)row * D_MODEL;
    float ss = 0.f;
    for (int i = threadIdx.x; i < D_MODEL; i += blockDim.x) {
        float v = xr[i];
        ss += v * v;
    }
    ss = block_reduce_sum(ss);
    float inv = rsqrtf(ss * (1.f / D_MODEL) + EPS);
    float* o = out + (size_t)row * D_MODEL;
    for (int i = threadIdx.x; i < D_MODEL; i += blockDim.x)
        o[i] = xr[i] * inv * w[i];
}

// ---------------- final: out = fuse + rmsnorm(x, w) ----------------
__global__ void final_kernel(const float* __restrict__ fuse, const float* __restrict__ x,
                             const float* __restrict__ w, float* __restrict__ out) {
    int row = blockIdx.x;
    const float* xr = x + (size_t)row * D_MODEL;
    float ss = 0.f;
    for (int i = threadIdx.x; i < D_MODEL; i += blockDim.x) {
        float v = xr[i];
        ss += v * v;
    }
    ss = block_reduce_sum(ss);
    float inv = rsqrtf(ss * (1.f / D_MODEL) + EPS);
    const float* f = fuse + (size_t)row * D_MODEL;
    float* o = out + (size_t)row * D_MODEL;
    for (int i = threadIdx.x; i < D_MODEL; i += blockDim.x)
        o[i] = f[i] + xr[i] * inv * w[i];
}

// ---------------- GEMM: C[M,N] = A[M,K] * W[N,K]^T (+ addSrc) ----------------
#define GBM 128
#define GBN 64
#define GBK 16
#define GTM 8
#define GTN 4
// 256 threads: tx = tid&15 (N), ty = tid>>4 (M)
__global__ __launch_bounds__(256) void gemm_nt_kernel(
    const float* __restrict__ A, const float* __restrict__ W,
    float* __restrict__ C, const float* __restrict__ addSrc,
    int M, int N, int K) {
    __shared__ float As[GBK][GBM + 4];
    __shared__ float Bs[GBK][GBN + 4];
    int tid = threadIdx.x;
    int tx = tid & 15, ty = tid >> 4;
    int bm = blockIdx.y * GBM;
    int bn = blockIdx.x * GBN;
    float acc[GTM][GTN];
    #pragma unroll
    for (int i = 0; i < GTM; ++i)
        #pragma unroll
        for (int j = 0; j < GTN; ++j) acc[i][j] = 0.f;

    int ktiles = (K + GBK - 1) / GBK;
    for (int kt = 0; kt < ktiles; ++kt) {
        int k0 = kt * GBK;
        #pragma unroll
        for (int i = 0; i < 8; ++i) {
            int idx = i * 256 + tid;
            int k = idx & 15, m = idx >> 4;
            int gm = bm + m, gk = k0 + k;
            As[k][m] = (gm < M && gk < K) ? A[(size_t)gm * K + gk] : 0.f;
        }
        #pragma unroll
        for (int i = 0; i < 4; ++i) {
            int idx = i * 256 + tid;
            int k = idx & 15, n = idx >> 4;
            int gn = bn + n, gk = k0 + k;
            Bs[k][n] = (gn < N && gk < K) ? W[(size_t)gn * K + gk] : 0.f;
        }
        __syncthreads();
        #pragma unroll
        for (int k = 0; k < GBK; ++k) {
            float a[GTM], b[GTN];
            #pragma unroll
            for (int i = 0; i < GTM; ++i) a[i] = As[k][ty * GTM + i];
            #pragma unroll
            for (int j = 0; j < GTN; ++j) b[j] = Bs[k][tx * GTN + j];
            #pragma unroll
            for (int i = 0; i < GTM; ++i)
                #pragma unroll
                for (int j = 0; j < GTN; ++j) acc[i][j] += a[i] * b[j];
        }
        __syncthreads();
    }
    #pragma unroll
    for (int i = 0; i < GTM; ++i) {
        int gm = bm + ty * GTM + i;
        if (gm >= M) continue;
        #pragma unroll
        for (int j = 0; j < GTN; ++j) {
            int gn = bn + tx * GTN + j;
            if (gn >= N) continue;
            float v = acc[i][j];
            if (addSrc) v += addSrc[(size_t)gm * N + gn];
            C[(size_t)gm * N + gn] = v;
        }
    }
}

// ---------------- causal depthwise conv (k=4) + bias + silu ----------------
__global__ void conv_silu_kernel(const float* __restrict__ xz, const float* __restrict__ cw,
                                 const float* __restrict__ cb, float* __restrict__ xc) {
    int d = blockIdx.x * 128 + threadIdx.x;
    if (d >= D_INNER) return;
    int l = blockIdx.y;
    int b = blockIdx.z;
    size_t rowbase = ((size_t)b * L_SEQ + l);
    const float* base = xz + rowbase * TWO_D_INNER + d;  // xi part (cols 0..515)
    float w0 = cw[d * 4 + 0], w1 = cw[d * 4 + 1], w2 = cw[d * 4 + 2], w3 = cw[d * 4 + 3];
    float acc = cb[d];
    if (l >= 3) acc += w0 * base[-3 * TWO_D_INNER];
    if (l >= 2) acc += w1 * base[-2 * TWO_D_INNER];
    if (l >= 1) acc += w2 * base[-1 * TWO_D_INNER];
    acc += w3 * base[0];
    float sig = 1.f / (1.f + __expf(-acc));
    xc[rowbase * D_INNER + d] = acc * sig;
}

// ---------------- dt = softplus(dt_lo @ dtw^T + dtb) ----------------
__global__ void dt_kernel(const float* __restrict__ xdbl, const float* __restrict__ dtw,
                          const float* __restrict__ dtb, float* __restrict__ dt) {
    int m = blockIdx.x;
    __shared__ float lo[DT_RANK];
    if (threadIdx.x < DT_RANK) lo[threadIdx.x] = xdbl[(size_t)m * XDBL_W + threadIdx.x];
    __syncthreads();
    for (int d = threadIdx.x; d < D_INNER; d += blockDim.x) {
        float acc = dtb[d];
        const float* wr = dtw + (size_t)d * DT_RANK;
        #pragma unroll
        for (int r = 0; r < DT_RANK; ++r) acc += lo[r] * wr[r];
        float sp = (acc > 20.f) ? acc : log1pf(__expf(acc));
        dt[(size_t)m * D_INNER + d] = sp;
    }
}

// ---------------- selective scan ----------------
// block: 128 threads = 4 warps; each warp = 2 channels x 16 states (lane = (dloc, s))
#define SCAN_CH 8
#define SCAN_T 128
__global__ __launch_bounds__(128) void scan_kernel(
    const float* __restrict__ dt, const float* __restrict__ u,
    const float* __restrict__ xdbl, const float* __restrict__ A_log,
    float* __restrict__ y) {
    __shared__ float s_dt[SCAN_CH][SCAN_T];
    __shared__ float s_u[SCAN_CH][SCAN_T];
    __shared__ float s_B[SCAN_T][16];
    __shared__ float s_C[SCAN_T][16];

    int b = blockIdx.y;
    int d0 = blockIdx.x * SCAN_CH;
    int tid = threadIdx.x;
    int lane = tid & 31, warp = tid >> 5;
    int s = lane & 15;
    int dloc = warp * 2 + (lane >> 4);
    int d = d0 + dloc;
    int dc = (d < D_INNER) ? d : (D_INNER - 1);

    float Aval = -__expf(A_log[(size_t)dc * D_STATE + s]);  // A = -exp(A_log)
    float h = 0.f;
    size_t base_bl = (size_t)b * L_SEQ;

    for (int l0 = 0; l0 < L_SEQ; l0 += SCAN_T) {
        // stage dt/u
        for (int idx = tid; idx < SCAN_CH * SCAN_T; idx += 128) {
            int ch = idx & (SCAN_CH - 1);
            int t = idx >> 3;
            int dd = d0 + ch;
            if (dd >= D_INNER) dd = D_INNER - 1;
            size_t g = (base_bl + l0 + t) * (size_t)D_INNER + dd;
            s_dt[ch][t] = dt[g];
            s_u[ch][t] = u[g];
        }
        // stage B, C
        for (int idx = tid; idx < SCAN_T * 16; idx += 128) {
            int ss = idx & 15;
            int t = idx >> 4;
            size_t g = (base_bl + l0 + t) * (size_t)XDBL_W;
            s_B[t][ss] = xdbl[g + DT_RANK + ss];
            s_C[t][ss] = xdbl[g + DT_RANK + D_STATE + ss];
        }
        __syncthreads();
        #pragma unroll 4
        for (int t = 0; t < SCAN_T; ++t) {
            float dtv = s_dt[dloc][t];
            float uv = s_u[dloc][t];
            float Bv = s_B[t][s];
            float Cv = s_C[t][s];
            float dA = __expf(dtv * Aval);
            h = dA * h + (dtv * uv) * Bv;
            float p = h * Cv;
            p += __shfl_xor_sync(0xffffffffu, p, 8);
            p += __shfl_xor_sync(0xffffffffu, p, 4);
            p += __shfl_xor_sync(0xffffffffu, p, 2);
            p += __shfl_xor_sync(0xffffffffu, p, 1);
            if (s == 0 && d < D_INNER)
                y[(base_bl + l0 + t) * (size_t)D_INNER + d] = p;
        }
        __syncthreads();
    }
}

// ---------------- gate: y2 = (y + u*D) * silu(z) ----------------
__global__ void gate_kernel(const float* __restrict__ y, const float* __restrict__ xc,
                            const float* __restrict__ xz, const float* __restrict__ Dp,
                            float* __restrict__ y2) {
    int idx = blockIdx.x * 256 + threadIdx.x;
    if (idx >= NTOK * D_INNER) return;
    int d = idx % D_INNER;
    int m = idx / D_INNER;
    float z = xz[(size_t)m * TWO_D_INNER + D_INNER + d];
    float sz = z / (1.f + __expf(-z));
    y2[idx] = (y[idx] + xc[idx] * Dp[d]) * sz;
}

// ---------------- host launch ----------------
extern "C" void kernel_launch(void* const* d_in, const int* in_sizes, int n_in,
                              void* d_out, int out_size) {
    const float* fuse      = (const float*)d_in[0];   // (B, L, 258)
    const float* norm_w    = (const float*)d_in[1];   // (4, 258)
    const float* in_proj_w = (const float*)d_in[2];   // (4, 1032, 258)
    const float* conv_w    = (const float*)d_in[3];   // (4, 516, 4)
    const float* conv_b    = (const float*)d_in[4];   // (4, 516)
    const float* x_proj_w  = (const float*)d_in[5];   // (4, 49, 516)
    const float* dt_proj_w = (const float*)d_in[6];   // (4, 516, 17)
    const float* dt_proj_b = (const float*)d_in[7];   // (4, 516)
    const float* A_log     = (const float*)d_in[8];   // (4, 516, 16)
    const float* D_param   = (const float*)d_in[9];   // (4, 516)
    const float* out_proj_w= (const float*)d_in[10];  // (4, 258, 516)
    const float* final_w   = (const float*)d_in[11];  // (258,)
    float* out = (float*)d_out;

    float *p_x, *p_xn, *p_xz, *p_xc, *p_xdbl, *p_dt, *p_y, *p_y2;
    cudaGetSymbolAddress((void**)&p_x, g_x);
    cudaGetSymbolAddress((void**)&p_xn, g_xn);
    cudaGetSymbolAddress((void**)&p_xz, g_xz);
    cudaGetSymbolAddress((void**)&p_xc, g_xc);
    cudaGetSymbolAddress((void**)&p_xdbl, g_xdbl);
    cudaGetSymbolAddress((void**)&p_dt, g_dt);
    cudaGetSymbolAddress((void**)&p_y, g_y);
    cudaGetSymbolAddress((void**)&p_y2, g_y2);

    // x = fuse_feature
    cudaMemcpyAsync(p_x, fuse, (size_t)NTOK * D_MODEL * sizeof(float),
                    cudaMemcpyDeviceToDevice);

    for (int i = 0; i < N_LAYERS; ++i) {
        const float* nw  = norm_w + (size_t)i * D_MODEL;
        const float* iw  = in_proj_w + (size_t)i * TWO_D_INNER * D_MODEL;
        const float* cw  = conv_w + (size_t)i * D_INNER * D_CONV;
        const float* cb  = conv_b + (size_t)i * D_INNER;
        const float* xpw = x_proj_w + (size_t)i * XDBL_W * D_INNER;
        const float* dtw = dt_proj_w + (size_t)i * D_INNER * DT_RANK;
        const float* dtb = dt_proj_b + (size_t)i * D_INNER;
        const float* Al  = A_log + (size_t)i * D_INNER * D_STATE;
        const float* Dp  = D_param + (size_t)i * D_INNER;
        const float* ow  = out_proj_w + (size_t)i * D_MODEL * D_INNER;

        // 1) rmsnorm
        rmsnorm_kernel<<<NTOK, 256>>>(p_x, nw, p_xn);

        // 2) in_proj GEMM: (8192,258) x (1032,258)^T -> (8192,1032)
        {
            dim3 grid((TWO_D_INNER + GBN - 1) / GBN, (NTOK + GBM - 1) / GBM);
            gemm_nt_kernel<<<grid, 256>>>(p_xn, iw, p_xz, nullptr,
                                          NTOK, TWO_D_INNER, D_MODEL);
        }

        // 3) conv + silu -> u
        {
            dim3 grid((D_INNER + 127) / 128, L_SEQ, B_SZ);
            conv_silu_kernel<<<grid, 128>>>(p_xz, cw, cb, p_xc);
        }

        // 4) x_proj GEMM: (8192,516) x (49,516)^T -> (8192,49)
        {
            dim3 grid((XDBL_W + GBN - 1) / GBN, (NTOK + GBM - 1) / GBM);
            gemm_nt_kernel<<<grid, 256>>>(p_xc, xpw, p_xdbl, nullptr,
                                          NTOK, XDBL_W, D_INNER);
        }

        // 5) dt = softplus(dt_lo @ dtw^T + dtb)
        dt_kernel<<<NTOK, 256>>>(p_xdbl, dtw, dtb, p_dt);

        // 6) selective scan
        {
            dim3 grid((D_INNER + SCAN_CH - 1) / SCAN_CH, B_SZ);
            scan_kernel<<<grid, 128>>>(p_dt, p_xc, p_xdbl, Al, p_y);
        }

        // 7) gate
        {
            int total = NTOK * D_INNER;
            gate_kernel<<<(total + 255) / 256, 256>>>(p_y, p_xc, p_xz, Dp, p_y2);
        }

        // 8) out_proj GEMM + residual: x = x + y2 @ ow^T
        {
            dim3 grid((D_MODEL + GBN - 1) / GBN, (NTOK + GBM - 1) / GBM);
            gemm_nt_kernel<<<grid, 256>>>(p_y2, ow, p_x, p_x,
                                          NTOK, D_MODEL, D_INNER);
        }
    }

    // final: out = fuse + rmsnorm(x, final_w)
    final_kernel<<<NTOK, 256>>>(fuse, p_x, final_w, out);

    (void)in_sizes; (void)n_in; (void)out_size;
}